// round 1
// baseline (speedup 1.0000x reference)
#include <cuda_runtime.h>
#include <math.h>

// Problem constants
constexpr int CDIM = 384;   // channels
constexpr int NPIX = 1024;  // h*w
constexpr int NB   = 32;    // batch

// Scratch (device globals: allocation-free per harness rules)
__device__ float g_q[NB * CDIM * NPIX];
__device__ float g_k[NB * CDIM * NPIX];
__device__ float g_v[NB * CDIM * NPIX];
__device__ float g_o[NB * CDIM * NPIX];
__device__ float g_s[NB * NPIX * NPIX];   // 32 * 1M floats = 128 MiB

// ---------------------------------------------------------------------------
// Projection GEMM: Y[b,d,n] = bias[d] + sum_c W[d,c] * X[b,c,n]
// grid (NPIX/64, CDIM/64, NB), block 256. OUTSEL: 0->g_q 1->g_k 2->g_v 3->Yext
// For OUTSEL==3 the input is g_o (final fuse proj) and output is the param.
// ---------------------------------------------------------------------------
template <int OUTSEL>
__global__ void proj_kernel(const float* __restrict__ W,
                            const float* __restrict__ bias,
                            const float* __restrict__ Xext,
                            float* __restrict__ Yext)
{
    __shared__ float As[16][64];  // [c][d]  (W tile, transposed)
    __shared__ float Bs[16][64];  // [c][n]  (X tile)

    float* Y = (OUTSEL == 0) ? g_q : (OUTSEL == 1) ? g_k : (OUTSEL == 2) ? g_v : Yext;
    const float* X = (OUTSEL == 3) ? g_o : Xext;

    const int n0 = blockIdx.x * 64;
    const int d0 = blockIdx.y * 64;
    const int b  = blockIdx.z;
    const int t  = threadIdx.x;
    const int tx = t & 15;        // n subtile
    const int ty = t >> 4;        // d subtile

    const float* Xb = X + (size_t)b * CDIM * NPIX;

    // load index helpers
    const int aw_d = t >> 2;         // 0..63
    const int aw_c = (t & 3) * 4;    // 0,4,8,12
    const int bw_c = t >> 4;         // 0..15
    const int bw_n = (t & 15) * 4;   // 0..60

    float acc[4][4] = {};

    for (int c0 = 0; c0 < CDIM; c0 += 16) {
        float4 wa = *reinterpret_cast<const float4*>(&W[(d0 + aw_d) * CDIM + c0 + aw_c]);
        As[aw_c + 0][aw_d] = wa.x;
        As[aw_c + 1][aw_d] = wa.y;
        As[aw_c + 2][aw_d] = wa.z;
        As[aw_c + 3][aw_d] = wa.w;
        *reinterpret_cast<float4*>(&Bs[bw_c][bw_n]) =
            *reinterpret_cast<const float4*>(&Xb[(size_t)(c0 + bw_c) * NPIX + n0 + bw_n]);
        __syncthreads();

#pragma unroll
        for (int k = 0; k < 16; ++k) {
            float4 a4 = *reinterpret_cast<const float4*>(&As[k][ty * 4]);
            float4 b4 = *reinterpret_cast<const float4*>(&Bs[k][tx * 4]);
            float av[4] = {a4.x, a4.y, a4.z, a4.w};
            float bw[4] = {b4.x, b4.y, b4.z, b4.w};
#pragma unroll
            for (int i = 0; i < 4; ++i)
#pragma unroll
                for (int j = 0; j < 4; ++j)
                    acc[i][j] = fmaf(av[i], bw[j], acc[i][j]);
        }
        __syncthreads();
    }

#pragma unroll
    for (int i = 0; i < 4; ++i) {
        const int d = d0 + ty * 4 + i;
        const float bb = bias[d];
        float4 r = make_float4(acc[i][0] + bb, acc[i][1] + bb, acc[i][2] + bb, acc[i][3] + bb);
        *reinterpret_cast<float4*>(&Y[((size_t)b * CDIM + d) * NPIX + n0 + tx * 4]) = r;
    }
}

// ---------------------------------------------------------------------------
// Scores: S[b,n,m] = scale * sum_c q[b,c,n] * k[b,c,m]
// grid (NPIX/64 (m), NPIX/64 (n), NB), block 256
// ---------------------------------------------------------------------------
__global__ void scores_kernel()
{
    __shared__ float As[16][64];  // [c][n]
    __shared__ float Bs[16][64];  // [c][m]

    const int m0 = blockIdx.x * 64;
    const int n0 = blockIdx.y * 64;
    const int b  = blockIdx.z;
    const int t  = threadIdx.x;
    const int tx = t & 15;   // m subtile
    const int ty = t >> 4;   // n subtile

    const float* Qb = g_q + (size_t)b * CDIM * NPIX;
    const float* Kb = g_k + (size_t)b * CDIM * NPIX;

    const int lc = t >> 4;          // 0..15
    const int ln = (t & 15) * 4;    // 0..60

    float acc[4][4] = {};

    for (int c0 = 0; c0 < CDIM; c0 += 16) {
        *reinterpret_cast<float4*>(&As[lc][ln]) =
            *reinterpret_cast<const float4*>(&Qb[(size_t)(c0 + lc) * NPIX + n0 + ln]);
        *reinterpret_cast<float4*>(&Bs[lc][ln]) =
            *reinterpret_cast<const float4*>(&Kb[(size_t)(c0 + lc) * NPIX + m0 + ln]);
        __syncthreads();

#pragma unroll
        for (int k = 0; k < 16; ++k) {
            float4 a4 = *reinterpret_cast<const float4*>(&As[k][ty * 4]);
            float4 b4 = *reinterpret_cast<const float4*>(&Bs[k][tx * 4]);
            float av[4] = {a4.x, a4.y, a4.z, a4.w};
            float bw[4] = {b4.x, b4.y, b4.z, b4.w};
#pragma unroll
            for (int i = 0; i < 4; ++i)
#pragma unroll
                for (int j = 0; j < 4; ++j)
                    acc[i][j] = fmaf(av[i], bw[j], acc[i][j]);
        }
        __syncthreads();
    }

    const float scale = rsqrtf((float)CDIM);
#pragma unroll
    for (int i = 0; i < 4; ++i) {
        float4 r = make_float4(acc[i][0] * scale, acc[i][1] * scale,
                               acc[i][2] * scale, acc[i][3] * scale);
        *reinterpret_cast<float4*>(
            &g_s[((size_t)b * NPIX + n0 + ty * 4 + i) * NPIX + m0 + tx * 4]) = r;
    }
}

// ---------------------------------------------------------------------------
// Row softmax over m. One CTA (128 threads) per row; 8 elements/thread.
// grid NB*NPIX, block 128
// ---------------------------------------------------------------------------
__global__ void softmax_kernel()
{
    const int row = blockIdx.x;
    float* p = g_s + (size_t)row * NPIX;
    const int t = threadIdx.x;

    float4 a = *reinterpret_cast<const float4*>(&p[t * 4]);
    float4 c = *reinterpret_cast<const float4*>(&p[512 + t * 4]);
    float v[8] = {a.x, a.y, a.z, a.w, c.x, c.y, c.z, c.w};

    float m = v[0];
#pragma unroll
    for (int i = 1; i < 8; ++i) m = fmaxf(m, v[i]);
#pragma unroll
    for (int o = 16; o > 0; o >>= 1) m = fmaxf(m, __shfl_xor_sync(0xffffffffu, m, o));

    __shared__ float rmax[4];
    __shared__ float rsum[4];
    const int w = t >> 5, l = t & 31;
    if (l == 0) rmax[w] = m;
    __syncthreads();
    const float mr = fmaxf(fmaxf(rmax[0], rmax[1]), fmaxf(rmax[2], rmax[3]));

    float s = 0.f;
#pragma unroll
    for (int i = 0; i < 8; ++i) { v[i] = __expf(v[i] - mr); s += v[i]; }
#pragma unroll
    for (int o = 16; o > 0; o >>= 1) s += __shfl_xor_sync(0xffffffffu, s, o);
    if (l == 0) rsum[w] = s;
    __syncthreads();
    const float inv = 1.f / (rsum[0] + rsum[1] + rsum[2] + rsum[3]);

    a = make_float4(v[0] * inv, v[1] * inv, v[2] * inv, v[3] * inv);
    c = make_float4(v[4] * inv, v[5] * inv, v[6] * inv, v[7] * inv);
    *reinterpret_cast<float4*>(&p[t * 4]) = a;
    *reinterpret_cast<float4*>(&p[512 + t * 4]) = c;
}

// ---------------------------------------------------------------------------
// Attention output: O[b,c,n] = sum_m v[b,c,m] * P[b,n,m]
// grid (NPIX/64 (n), CDIM/64 (c), NB), block 256
// ---------------------------------------------------------------------------
__global__ void av_kernel()
{
    __shared__ float As[16][64];  // [m][c]  (V tile, transposed)
    __shared__ float Bs[16][64];  // [m][n]  (P tile, transposed)

    const int n0 = blockIdx.x * 64;
    const int c0 = blockIdx.y * 64;
    const int b  = blockIdx.z;
    const int t  = threadIdx.x;
    const int tx = t & 15;   // n subtile
    const int ty = t >> 4;   // c subtile

    const float* Vb = g_v + (size_t)b * CDIM * NPIX;
    const float* Pb = g_s + (size_t)b * NPIX * NPIX;

    const int r64 = t >> 2;         // 0..63 (c row for V, n row for P)
    const int m4  = (t & 3) * 4;    // 0,4,8,12

    float acc[4][4] = {};

    for (int m0 = 0; m0 < NPIX; m0 += 16) {
        float4 va = *reinterpret_cast<const float4*>(&Vb[(size_t)(c0 + r64) * NPIX + m0 + m4]);
        As[m4 + 0][r64] = va.x;
        As[m4 + 1][r64] = va.y;
        As[m4 + 2][r64] = va.z;
        As[m4 + 3][r64] = va.w;
        float4 pa = *reinterpret_cast<const float4*>(&Pb[(size_t)(n0 + r64) * NPIX + m0 + m4]);
        Bs[m4 + 0][r64] = pa.x;
        Bs[m4 + 1][r64] = pa.y;
        Bs[m4 + 2][r64] = pa.z;
        Bs[m4 + 3][r64] = pa.w;
        __syncthreads();

#pragma unroll
        for (int k = 0; k < 16; ++k) {
            float4 a4 = *reinterpret_cast<const float4*>(&As[k][ty * 4]);
            float4 b4 = *reinterpret_cast<const float4*>(&Bs[k][tx * 4]);
            float av[4] = {a4.x, a4.y, a4.z, a4.w};
            float bw[4] = {b4.x, b4.y, b4.z, b4.w};
#pragma unroll
            for (int i = 0; i < 4; ++i)
#pragma unroll
                for (int j = 0; j < 4; ++j)
                    acc[i][j] = fmaf(av[i], bw[j], acc[i][j]);
        }
        __syncthreads();
    }

#pragma unroll
    for (int i = 0; i < 4; ++i) {
        float4 r = make_float4(acc[i][0], acc[i][1], acc[i][2], acc[i][3]);
        *reinterpret_cast<float4*>(
            &g_o[((size_t)b * CDIM + c0 + ty * 4 + i) * NPIX + n0 + tx * 4]) = r;
    }
}

// ---------------------------------------------------------------------------
// Launch
// ---------------------------------------------------------------------------
extern "C" void kernel_launch(void* const* d_in, const int* in_sizes, int n_in,
                              void* d_out, int out_size)
{
    const float* rgb = (const float*)d_in[0];
    const float* ms  = (const float*)d_in[1];
    const float* Wq  = (const float*)d_in[2];
    const float* bq  = (const float*)d_in[3];
    const float* Wk  = (const float*)d_in[4];
    const float* bk  = (const float*)d_in[5];
    const float* Wv  = (const float*)d_in[6];
    const float* bv  = (const float*)d_in[7];
    const float* Wf  = (const float*)d_in[8];
    const float* bf  = (const float*)d_in[9];
    float* out = (float*)d_out;

    dim3 blk(256);
    dim3 gproj(NPIX / 64, CDIM / 64, NB);   // (16, 6, 32)
    dim3 gsc(NPIX / 64, NPIX / 64, NB);     // (16, 16, 32)

    proj_kernel<0><<<gproj, blk>>>(Wq, bq, rgb, nullptr);
    proj_kernel<1><<<gproj, blk>>>(Wk, bk, ms, nullptr);
    proj_kernel<2><<<gproj, blk>>>(Wv, bv, ms, nullptr);
    scores_kernel<<<gsc, blk>>>();
    softmax_kernel<<<NB * NPIX, 128>>>();
    av_kernel<<<gproj, blk>>>();
    proj_kernel<3><<<gproj, blk>>>(Wf, bf, nullptr, out);
}

// round 5
// speedup vs baseline: 2.0413x; 2.0413x over previous
#include <cuda_runtime.h>
#include <cuda_bf16.h>
#include <math.h>
#include <stdint.h>

using bf16 = __nv_bfloat16;

constexpr int NB = 32;
constexpr int CD = 384;    // channels
constexpr int NP = 1024;   // pixels

// ---------------------------------------------------------------------------
// Device scratch (allocation-free). Split layout: [row][ hi(0..K-1) | lo(K..2K-1) ]
// ---------------------------------------------------------------------------
__device__ __align__(128) bf16  g_rgbT[(size_t)NB * NP * (2 * CD)];   // [b][n][c']
__device__ __align__(128) bf16  g_msT [(size_t)NB * NP * (2 * CD)];   // [b][n][c']
__device__ __align__(128) bf16  g_Wqs[CD * (2 * CD)];
__device__ __align__(128) bf16  g_Wks[CD * (2 * CD)];
__device__ __align__(128) bf16  g_Wvs[CD * (2 * CD)];
__device__ __align__(128) bf16  g_Wfs[CD * (2 * CD)];
__device__ __align__(128) bf16  g_qs[(size_t)NB * NP * (2 * CD)];     // [b][n][d']
__device__ __align__(128) bf16  g_ks[(size_t)NB * NP * (2 * CD)];     // [b][m][d']
__device__ __align__(128) bf16  g_vs[(size_t)NB * CD * (2 * NP)];     // [b][c][m']
__device__ __align__(128) float g_Sc[(size_t)NB * NP * NP];           // scores fp32
__device__ __align__(128) bf16  g_Ps[(size_t)NB * NP * (2 * NP)];     // softmax split
__device__ __align__(128) bf16  g_os[(size_t)NB * NP * (2 * CD)];     // [b][n][c']

// ---------------------------------------------------------------------------
// Base-target PTX helpers (sm_80-class: cp.async / ldmatrix / mma.sync)
// ---------------------------------------------------------------------------
__device__ __forceinline__ uint32_t su32(const void* p) {
    uint32_t a;
    asm("{ .reg .u64 t; cvta.to.shared.u64 t, %1; cvt.u32.u64 %0, t; }" : "=r"(a) : "l"(p));
    return a;
}
__device__ __forceinline__ void cpa16(uint32_t s, const void* g) {
    asm volatile("cp.async.cg.shared.global [%0], [%1], 16;" :: "r"(s), "l"(g));
}
__device__ __forceinline__ void cp_commit() {
    asm volatile("cp.async.commit_group;" ::: "memory");
}
template <int N>
__device__ __forceinline__ void cp_wait() {
    asm volatile("cp.async.wait_group %0;" :: "n"(N) : "memory");
}
__device__ __forceinline__ void ldsm4(uint32_t* r, uint32_t addr) {
    asm volatile("ldmatrix.sync.aligned.m8n8.x4.shared.b16 {%0,%1,%2,%3}, [%4];"
                 : "=r"(r[0]), "=r"(r[1]), "=r"(r[2]), "=r"(r[3]) : "r"(addr));
}
__device__ __forceinline__ void mma_bf16(float* d, const uint32_t* a, uint32_t b0, uint32_t b1) {
    asm volatile(
        "mma.sync.aligned.m16n8k16.row.col.f32.bf16.bf16.f32 "
        "{%0,%1,%2,%3}, {%4,%5,%6,%7}, {%8,%9}, {%0,%1,%2,%3};"
        : "+f"(d[0]), "+f"(d[1]), "+f"(d[2]), "+f"(d[3])
        : "r"(a[0]), "r"(a[1]), "r"(a[2]), "r"(a[3]), "r"(b0), "r"(b1));
}

__device__ __forceinline__ void split2(float f, bf16& h, bf16& l) {
    h = __float2bfloat16(f);
    l = __float2bfloat16(f - __bfloat162float(h));
}

// ---------------------------------------------------------------------------
// Pack kernels
// ---------------------------------------------------------------------------
// W [d][c] fp32 -> [d][hi|lo] bf16
__global__ void pack_w(const float* __restrict__ W, bf16* __restrict__ out) {
    int idx = blockIdx.x * 256 + threadIdx.x;   // 384*384 = 576*256
    int r = idx / CD, c = idx % CD;
    float f = W[idx];
    bf16 h, l; split2(f, h, l);
    out[(size_t)r * (2 * CD) + c] = h;
    out[(size_t)r * (2 * CD) + CD + c] = l;
}

// X [b][c][n] fp32 -> out [b][n][hi(c)|lo(c)] bf16 (transpose + split)
__global__ void pack_t(const float* __restrict__ X, bf16* __restrict__ out) {
    __shared__ float t[32][33];
    int b = blockIdx.z;
    int n0 = blockIdx.x * 32, c0 = blockIdx.y * 32;
    int tx = threadIdx.x, ty = threadIdx.y;   // (32, 8)
    const float* Xb = X + (size_t)b * CD * NP;
    bf16* Ob = out + (size_t)b * NP * (2 * CD);
#pragma unroll
    for (int i = 0; i < 4; ++i)
        t[ty + 8 * i][tx] = Xb[(size_t)(c0 + ty + 8 * i) * NP + n0 + tx];
    __syncthreads();
#pragma unroll
    for (int i = 0; i < 4; ++i) {
        int n = n0 + ty + 8 * i;
        float f = t[tx][ty + 8 * i];
        bf16 h, l; split2(f, h, l);
        Ob[(size_t)n * (2 * CD) + c0 + tx] = h;
        Ob[(size_t)n * (2 * CD) + CD + c0 + tx] = l;
    }
}

// ---------------------------------------------------------------------------
// Generic split-bf16 GEMM via mma.sync (HMMA).
// D[128 A-rows][128 B-rows] = sum over 3 segs of A[m][aoff+k]*B[n][boff+k].
// A rows tile = blockIdx.y*128, B rows tile = blockIdx.x*128, batch = blockIdx.z.
// EPI: 0 = split-bf16 out, 1 = fp32*scale out, 2 = fp32 transposed out (d_out).
// BIAS: 0 none, 1 by B-row(col of D), 2 by A-row.
// ---------------------------------------------------------------------------
constexpr int SROWB = 80;       // padded smem row bytes (32 bf16 = 64B + 16B pad)
constexpr int STAGEB = 128 * SROWB;        // 10240 per operand
constexpr int BUFB   = 2 * STAGEB;         // A+B per stage: 20480
constexpr int SMEMSZ = 128 * 129 * 4;      // 66048 (epilogue stage; > 2*BUFB=40960)

template <int K, int EPI, int BIAS>
__global__ __launch_bounds__(256)
void mm_kernel(const bf16* __restrict__ A, const bf16* __restrict__ B,
               void* __restrict__ Out, const float* __restrict__ bias,
               size_t aBatch, size_t bBatch, size_t oBatch,
               int outRowStride, int loOff)
{
    extern __shared__ __align__(16) char dynsmem[];

    constexpr int CH  = K / 32;     // chunks per segment
    constexpr int NCH = 3 * CH;
    constexpr int RS  = 2 * K;      // operand row stride (elems)

    const int tid  = threadIdx.x;
    const int wid  = tid >> 5;
    const int lane = tid & 31;
    const int warp_m = wid & 1;          // 2 m-blocks of 64
    const int warp_n = wid >> 1;         // 4 n-blocks of 32
    const int m0 = blockIdx.y * 128;
    const int n0 = blockIdx.x * 128;
    const int b  = blockIdx.z;

    const bf16* Ab = A + (size_t)b * aBatch + (size_t)m0 * RS;
    const bf16* Bb = B + (size_t)b * bBatch + (size_t)n0 * RS;

    const uint32_t smem_u = su32(dynsmem);

    const int segA[3] = { 0, 0, K };
    const int segB[3] = { 0, K, 0 };

    // load mapping: task = tid + 256*j ; row = task>>2 ; col16 = task&3
    const int lrow0 = tid >> 2;
    const int lc16  = tid & 3;

    float acc[4][4][4] = {};

    // ldmatrix per-thread address components
    const int a_row = warp_m * 64 + (lane & 15);        // + mt*16
    const int a_kof = 8 * (lane >> 4);                  // + ks
    const int b_row = warp_n * 32 + (lane & 7) + 8 * (lane >> 4);  // + np*16
    const int b_kof = 8 * ((lane >> 3) & 1);            // + ks

    auto load_chunk = [&](int i, int buf) {
        const int seg = i / CH, kc = i % CH;
        const int aoff = segA[seg] + kc * 32;
        const int boff = segB[seg] + kc * 32;
        const uint32_t sa = smem_u + buf * BUFB;
        const uint32_t sb = sa + STAGEB;
#pragma unroll
        for (int j = 0; j < 2; ++j) {
            const int row = lrow0 + 64 * j;
            cpa16(sa + row * SROWB + lc16 * 16, Ab + (size_t)row * RS + aoff + lc16 * 8);
            cpa16(sb + row * SROWB + lc16 * 16, Bb + (size_t)row * RS + boff + lc16 * 8);
        }
        cp_commit();
    };

    load_chunk(0, 0);

    for (int i = 0; i < NCH; ++i) {
        if (i + 1 < NCH) { load_chunk(i + 1, (i + 1) & 1); cp_wait<1>(); }
        else             { cp_wait<0>(); }
        __syncthreads();

        const uint32_t sa = smem_u + (i & 1) * BUFB;
        const uint32_t sb = sa + STAGEB;
#pragma unroll
        for (int ks = 0; ks < 32; ks += 16) {
            uint32_t af[4][4];
#pragma unroll
            for (int mt = 0; mt < 4; ++mt)
                ldsm4(af[mt], sa + (a_row + mt * 16) * SROWB + (ks + a_kof) * 2);
            uint32_t bfr[2][4];
#pragma unroll
            for (int np = 0; np < 2; ++np)
                ldsm4(bfr[np], sb + (b_row + np * 16) * SROWB + (ks + b_kof) * 2);
#pragma unroll
            for (int mt = 0; mt < 4; ++mt)
#pragma unroll
                for (int nt = 0; nt < 4; ++nt)
                    mma_bf16(acc[mt][nt], af[mt],
                             bfr[nt >> 1][2 * (nt & 1)], bfr[nt >> 1][2 * (nt & 1) + 1]);
        }
        __syncthreads();
    }

    // ---- Epilogue: accum frags -> padded smem stage -> global ----
    float* st = reinterpret_cast<float*>(dynsmem);
    const int lr  = lane >> 2;
    const int lc2 = 2 * (lane & 3);
#pragma unroll
    for (int mt = 0; mt < 4; ++mt)
#pragma unroll
        for (int nt = 0; nt < 4; ++nt) {
            const int gr = warp_m * 64 + mt * 16 + lr;
            const int gc = warp_n * 32 + nt * 8 + lc2;
            st[gr * 129 + gc]           = acc[mt][nt][0];
            st[gr * 129 + gc + 1]       = acc[mt][nt][1];
            st[(gr + 8) * 129 + gc]     = acc[mt][nt][2];
            st[(gr + 8) * 129 + gc + 1] = acc[mt][nt][3];
        }
    __syncthreads();

    if (EPI == 0) {
        bf16* outp = reinterpret_cast<bf16*>(Out) + (size_t)b * oBatch;
        for (int idx = tid; idx < 128 * 64; idx += 256) {
            const int r  = idx >> 6;
            const int c2 = (idx & 63) * 2;
            float f0 = st[r * 129 + c2];
            float f1 = st[r * 129 + c2 + 1];
            if (BIAS == 1) { f0 += bias[n0 + c2]; f1 += bias[n0 + c2 + 1]; }
            if (BIAS == 2) { const float bb = bias[m0 + r]; f0 += bb; f1 += bb; }
            bf16 h0, l0, h1, l1;
            split2(f0, h0, l0); split2(f1, h1, l1);
            const size_t base = (size_t)(m0 + r) * outRowStride + n0;
            __nv_bfloat162 hv; hv.x = h0; hv.y = h1;
            __nv_bfloat162 lv; lv.x = l0; lv.y = l1;
            *reinterpret_cast<__nv_bfloat162*>(outp + base + c2) = hv;
            *reinterpret_cast<__nv_bfloat162*>(outp + base + loOff + c2) = lv;
        }
    } else if (EPI == 1) {
        const float SCALE = 0.05103103630798288f;  // 1/sqrt(384)
        float* outp = reinterpret_cast<float*>(Out) + (size_t)b * oBatch;
        for (int idx = tid; idx < 128 * 32; idx += 256) {
            const int r  = idx >> 5;
            const int c4 = (idx & 31) * 4;
            float4 v;
            v.x = st[r * 129 + c4]     * SCALE;
            v.y = st[r * 129 + c4 + 1] * SCALE;
            v.z = st[r * 129 + c4 + 2] * SCALE;
            v.w = st[r * 129 + c4 + 3] * SCALE;
            *reinterpret_cast<float4*>(&outp[(size_t)(m0 + r) * outRowStride + n0 + c4]) = v;
        }
    } else {
        // final: D[n][d] -> out[b][d][n] (+ bias by d = col)
        float* outp = reinterpret_cast<float*>(Out) + (size_t)b * oBatch;
        for (int idx = tid; idx < 128 * 128; idx += 256) {
            const int r = idx & 127;       // n within tile (coalesced in out)
            const int c = idx >> 7;        // d within tile
            float f = st[r * 129 + c];
            if (BIAS == 1) f += bias[n0 + c];
            outp[(size_t)(n0 + c) * outRowStride + m0 + r] = f;
        }
    }
}

// ---------------------------------------------------------------------------
// Softmax over m, writes split-bf16 P: [n][ hi(m) | lo(m) ]
// ---------------------------------------------------------------------------
__global__ void softmax_kernel()
{
    const size_t row = blockIdx.x;
    const float* p = g_Sc + row * NP;
    bf16* po = g_Ps + row * (size_t)(2 * NP);
    const int t = threadIdx.x;

    float4 a = *reinterpret_cast<const float4*>(&p[t * 4]);
    float4 c = *reinterpret_cast<const float4*>(&p[512 + t * 4]);
    float v[8] = {a.x, a.y, a.z, a.w, c.x, c.y, c.z, c.w};

    float m = v[0];
#pragma unroll
    for (int i = 1; i < 8; ++i) m = fmaxf(m, v[i]);
#pragma unroll
    for (int o = 16; o > 0; o >>= 1) m = fmaxf(m, __shfl_xor_sync(0xffffffffu, m, o));

    __shared__ float rmax[4];
    __shared__ float rsum[4];
    const int w = t >> 5, l = t & 31;
    if (l == 0) rmax[w] = m;
    __syncthreads();
    const float mr = fmaxf(fmaxf(rmax[0], rmax[1]), fmaxf(rmax[2], rmax[3]));

    float s = 0.f;
#pragma unroll
    for (int i = 0; i < 8; ++i) { v[i] = __expf(v[i] - mr); s += v[i]; }
#pragma unroll
    for (int o = 16; o > 0; o >>= 1) s += __shfl_xor_sync(0xffffffffu, s, o);
    if (l == 0) rsum[w] = s;
    __syncthreads();
    const float inv = 1.f / (rsum[0] + rsum[1] + rsum[2] + rsum[3]);

#pragma unroll
    for (int half = 0; half < 2; ++half) {
        const int col = half * 512 + t * 4;
#pragma unroll
        for (int k2 = 0; k2 < 2; ++k2) {
            float f0 = v[half * 4 + k2 * 2 + 0] * inv;
            float f1 = v[half * 4 + k2 * 2 + 1] * inv;
            bf16 h0, l0, h1, l1;
            split2(f0, h0, l0); split2(f1, h1, l1);
            __nv_bfloat162 hv; hv.x = h0; hv.y = h1;
            __nv_bfloat162 lv; lv.x = l0; lv.y = l1;
            *reinterpret_cast<__nv_bfloat162*>(po + col + k2 * 2) = hv;
            *reinterpret_cast<__nv_bfloat162*>(po + NP + col + k2 * 2) = lv;
        }
    }
}

// ---------------------------------------------------------------------------
// Launch
// ---------------------------------------------------------------------------
extern "C" void kernel_launch(void* const* d_in, const int* in_sizes, int n_in,
                              void* d_out, int out_size)
{
    const float* rgb = (const float*)d_in[0];
    const float* ms  = (const float*)d_in[1];
    const float* Wq  = (const float*)d_in[2];
    const float* bq  = (const float*)d_in[3];
    const float* Wk  = (const float*)d_in[4];
    const float* bk  = (const float*)d_in[5];
    const float* Wv  = (const float*)d_in[6];
    const float* bv  = (const float*)d_in[7];
    const float* Wf  = (const float*)d_in[8];
    const float* bf  = (const float*)d_in[9];
    float* out = (float*)d_out;

    void *p_rgbT, *p_msT, *p_Wqs, *p_Wks, *p_Wvs, *p_Wfs;
    void *p_qs, *p_ks, *p_vs, *p_Sc, *p_Ps, *p_os;
    cudaGetSymbolAddress(&p_rgbT, g_rgbT);
    cudaGetSymbolAddress(&p_msT,  g_msT);
    cudaGetSymbolAddress(&p_Wqs,  g_Wqs);
    cudaGetSymbolAddress(&p_Wks,  g_Wks);
    cudaGetSymbolAddress(&p_Wvs,  g_Wvs);
    cudaGetSymbolAddress(&p_Wfs,  g_Wfs);
    cudaGetSymbolAddress(&p_qs,   g_qs);
    cudaGetSymbolAddress(&p_ks,   g_ks);
    cudaGetSymbolAddress(&p_vs,   g_vs);
    cudaGetSymbolAddress(&p_Sc,   g_Sc);
    cudaGetSymbolAddress(&p_Ps,   g_Ps);
    cudaGetSymbolAddress(&p_os,   g_os);

    cudaFuncSetAttribute(mm_kernel<384, 0, 1>,  cudaFuncAttributeMaxDynamicSharedMemorySize, SMEMSZ);
    cudaFuncSetAttribute(mm_kernel<384, 0, 2>,  cudaFuncAttributeMaxDynamicSharedMemorySize, SMEMSZ);
    cudaFuncSetAttribute(mm_kernel<384, 1, 0>,  cudaFuncAttributeMaxDynamicSharedMemorySize, SMEMSZ);
    cudaFuncSetAttribute(mm_kernel<1024, 0, 0>, cudaFuncAttributeMaxDynamicSharedMemorySize, SMEMSZ);
    cudaFuncSetAttribute(mm_kernel<384, 2, 1>,  cudaFuncAttributeMaxDynamicSharedMemorySize, SMEMSZ);

    // pack
    pack_t<<<dim3(32, 12, NB), dim3(32, 8)>>>(rgb, (bf16*)p_rgbT);
    pack_t<<<dim3(32, 12, NB), dim3(32, 8)>>>(ms,  (bf16*)p_msT);
    pack_w<<<576, 256>>>(Wq, (bf16*)p_Wqs);
    pack_w<<<576, 256>>>(Wk, (bf16*)p_Wks);
    pack_w<<<576, 256>>>(Wv, (bf16*)p_Wvs);
    pack_w<<<576, 256>>>(Wf, (bf16*)p_Wfs);

    const size_t xB = (size_t)NP * (2 * CD);
    const size_t vB = (size_t)CD * (2 * NP);
    const size_t sB = (size_t)NP * NP;

    // q = rgb^T * Wq^T : D[n][d]
    mm_kernel<384, 0, 1><<<dim3(3, 8, NB), 256, SMEMSZ>>>(
        (bf16*)p_rgbT, (bf16*)p_Wqs, p_qs, bq, xB, 0, xB, 2 * CD, CD);
    // k = ms^T * Wk^T : D[m][d]
    mm_kernel<384, 0, 1><<<dim3(3, 8, NB), 256, SMEMSZ>>>(
        (bf16*)p_msT, (bf16*)p_Wks, p_ks, bk, xB, 0, xB, 2 * CD, CD);
    // v = Wv * ms : D[c][m]  (bias by row)
    mm_kernel<384, 0, 2><<<dim3(8, 3, NB), 256, SMEMSZ>>>(
        (bf16*)p_Wvs, (bf16*)p_msT, p_vs, bv, 0, xB, vB, 2 * NP, NP);
    // scores: D[n][m] fp32 * 1/sqrt(C)
    mm_kernel<384, 1, 0><<<dim3(8, 8, NB), 256, SMEMSZ>>>(
        (bf16*)p_qs, (bf16*)p_ks, p_Sc, nullptr, xB, xB, sB, NP, 0);
    // softmax + split-pack P
    softmax_kernel<<<NB * NP, 128>>>();
    // O^T[n][c] = P * v^T
    mm_kernel<1024, 0, 0><<<dim3(3, 8, NB), 256, SMEMSZ>>>(
        (bf16*)p_Ps, (bf16*)p_vs, p_os, nullptr, (size_t)NP * (2 * NP), vB, xB, 2 * CD, CD);
    // final: D[n][d] -> out[b][d][n] (+bias by d)
    mm_kernel<384, 2, 1><<<dim3(3, 8, NB), 256, SMEMSZ>>>(
        (bf16*)p_os, (bf16*)p_Wfs, out, bf, xB, 0, (size_t)CD * NP, NP, 0);
}

// round 6
// speedup vs baseline: 2.5565x; 1.2524x over previous
#include <cuda_runtime.h>
#include <cuda_bf16.h>
#include <math.h>
#include <stdint.h>

using bf16 = __nv_bfloat16;

constexpr int NB = 32;
constexpr int CD = 384;    // channels
constexpr int NP = 1024;   // pixels

// ---------------------------------------------------------------------------
// Device scratch (allocation-free). Split layout: [row][ hi(0..K-1) | lo(K..2K-1) ]
// ---------------------------------------------------------------------------
__device__ __align__(128) bf16  g_rgbT[(size_t)NB * NP * (2 * CD)];   // [b][n][c']
__device__ __align__(128) bf16  g_msT [(size_t)NB * NP * (2 * CD)];   // [b][n][c']
__device__ __align__(128) bf16  g_Wqs[CD * (2 * CD)];
__device__ __align__(128) bf16  g_Wks[CD * (2 * CD)];
__device__ __align__(128) bf16  g_Wvs[CD * (2 * CD)];
__device__ __align__(128) bf16  g_Wfs[CD * (2 * CD)];
__device__ __align__(128) bf16  g_qs[(size_t)NB * NP * (2 * CD)];     // [b][n][d']
__device__ __align__(128) bf16  g_ks[(size_t)NB * NP * (2 * CD)];     // [b][m][d']
__device__ __align__(128) bf16  g_vs[(size_t)NB * CD * (2 * NP)];     // [b][c][m']
__device__ __align__(128) float g_Sc[(size_t)NB * NP * NP];           // scores fp32
__device__ __align__(128) bf16  g_Ps[(size_t)NB * NP * (2 * NP)];     // softmax split
__device__ __align__(128) bf16  g_os[(size_t)NB * NP * (2 * CD)];     // [b][n][c']

// ---------------------------------------------------------------------------
// Base-target PTX helpers (sm_80-class: cp.async / ldmatrix / mma.sync)
// ---------------------------------------------------------------------------
__device__ __forceinline__ uint32_t su32(const void* p) {
    uint32_t a;
    asm("{ .reg .u64 t; cvta.to.shared.u64 t, %1; cvt.u32.u64 %0, t; }" : "=r"(a) : "l"(p));
    return a;
}
__device__ __forceinline__ void cpa16(uint32_t s, const void* g) {
    asm volatile("cp.async.cg.shared.global [%0], [%1], 16;" :: "r"(s), "l"(g));
}
__device__ __forceinline__ void cp_commit() {
    asm volatile("cp.async.commit_group;" ::: "memory");
}
template <int N>
__device__ __forceinline__ void cp_wait() {
    asm volatile("cp.async.wait_group %0;" :: "n"(N) : "memory");
}
__device__ __forceinline__ void ldsm4(uint32_t* r, uint32_t addr) {
    asm volatile("ldmatrix.sync.aligned.m8n8.x4.shared.b16 {%0,%1,%2,%3}, [%4];"
                 : "=r"(r[0]), "=r"(r[1]), "=r"(r[2]), "=r"(r[3]) : "r"(addr));
}
__device__ __forceinline__ void mma_bf16(float* d, const uint32_t* a, uint32_t b0, uint32_t b1) {
    asm volatile(
        "mma.sync.aligned.m16n8k16.row.col.f32.bf16.bf16.f32 "
        "{%0,%1,%2,%3}, {%4,%5,%6,%7}, {%8,%9}, {%0,%1,%2,%3};"
        : "+f"(d[0]), "+f"(d[1]), "+f"(d[2]), "+f"(d[3])
        : "r"(a[0]), "r"(a[1]), "r"(a[2]), "r"(a[3]), "r"(b0), "r"(b1));
}

__device__ __forceinline__ void split2(float f, bf16& h, bf16& l) {
    h = __float2bfloat16(f);
    l = __float2bfloat16(f - __bfloat162float(h));
}

// ---------------------------------------------------------------------------
// Pack kernels (merged: one launch for both X tensors, one for all 4 weights)
// ---------------------------------------------------------------------------
// z<NB: rgb batch z ; z>=NB: ms batch z-NB
__global__ void pack_x(const float* __restrict__ Xr, const float* __restrict__ Xm) {
    __shared__ float t[32][33];
    int z = blockIdx.z;
    const float* X = (z < NB) ? Xr : Xm;
    bf16* out = (z < NB) ? g_rgbT : g_msT;
    int b = (z < NB) ? z : z - NB;
    int n0 = blockIdx.x * 32, c0 = blockIdx.y * 32;
    int tx = threadIdx.x, ty = threadIdx.y;   // (32, 8)
    const float* Xb = X + (size_t)b * CD * NP;
    bf16* Ob = out + (size_t)b * NP * (2 * CD);
#pragma unroll
    for (int i = 0; i < 4; ++i)
        t[ty + 8 * i][tx] = Xb[(size_t)(c0 + ty + 8 * i) * NP + n0 + tx];
    __syncthreads();
#pragma unroll
    for (int i = 0; i < 4; ++i) {
        int n = n0 + ty + 8 * i;
        float f = t[tx][ty + 8 * i];
        bf16 h, l; split2(f, h, l);
        Ob[(size_t)n * (2 * CD) + c0 + tx] = h;
        Ob[(size_t)n * (2 * CD) + CD + c0 + tx] = l;
    }
}

// blockIdx.y selects which weight
__global__ void pack_w4(const float* __restrict__ W0, const float* __restrict__ W1,
                        const float* __restrict__ W2, const float* __restrict__ W3) {
    int idx = blockIdx.x * 256 + threadIdx.x;   // 384*384 = 576*256
    int which = blockIdx.y;
    const float* W = (which == 0) ? W0 : (which == 1) ? W1 : (which == 2) ? W2 : W3;
    bf16* out = (which == 0) ? g_Wqs : (which == 1) ? g_Wks : (which == 2) ? g_Wvs : g_Wfs;
    int r = idx / CD, c = idx % CD;
    float f = W[idx];
    bf16 h, l; split2(f, h, l);
    out[(size_t)r * (2 * CD) + c] = h;
    out[(size_t)r * (2 * CD) + CD + c] = l;
}

// ---------------------------------------------------------------------------
// Generic split-bf16 GEMM via mma.sync (HMMA). K-chunk = 64.
// D[128 A-rows][128 B-rows] = sum over 3 segs of A[m][aoff+k]*B[n][boff+k].
// EPI: 0 = split-bf16 out, 1 = fp32*scale out, 2 = fp32 transposed out (d_out).
// BIAS: 0 none, 1 by B-row(col of D), 2 by A-row.
// ---------------------------------------------------------------------------
constexpr int KC     = 64;                 // K elems per chunk
constexpr int SROWB  = 144;                // 64 bf16 = 128B + 16B pad
constexpr int STAGEB = 128 * SROWB;        // 18432 per operand
constexpr int BUFB   = 2 * STAGEB;         // A+B per stage: 36864
constexpr int SMEMSZ = 2 * BUFB;           // 73728 (>= epilogue 128*129*4=66048)

template <int K, int EPI, int BIAS>
__global__ __launch_bounds__(256, 2)
void mm_kernel(const bf16* __restrict__ A, const bf16* __restrict__ B,
               void* __restrict__ Out, const float* __restrict__ bias,
               size_t aBatch, size_t bBatch, size_t oBatch,
               int outRowStride, int loOff)
{
    extern __shared__ __align__(16) char dynsmem[];

    constexpr int CH  = K / KC;     // chunks per segment
    constexpr int NCH = 3 * CH;
    constexpr int RS  = 2 * K;      // operand row stride (elems)

    const int tid  = threadIdx.x;
    const int wid  = tid >> 5;
    const int lane = tid & 31;
    const int warp_m = wid & 1;          // 2 m-blocks of 64
    const int warp_n = wid >> 1;         // 4 n-blocks of 32
    const int m0 = blockIdx.y * 128;
    const int n0 = blockIdx.x * 128;
    const int b  = blockIdx.z;

    const bf16* Ab = A + (size_t)b * aBatch + (size_t)m0 * RS;
    const bf16* Bb = B + (size_t)b * bBatch + (size_t)n0 * RS;

    const uint32_t smem_u = su32(dynsmem);

    const int segA[3] = { 0, 0, K };
    const int segB[3] = { 0, K, 0 };

    // load mapping: task = tid + 256*j (j=0..3); row = task>>3, c16 = task&7
    const int lrow0 = tid >> 3;
    const int lc16  = tid & 7;

    float acc[4][4][4] = {};

    // ldmatrix per-thread address components
    const int a_row = warp_m * 64 + (lane & 15);        // + mt*16
    const int a_kof = 8 * (lane >> 4);                  // + ks
    const int b_row = warp_n * 32 + (lane & 7) + 8 * (lane >> 4);  // + np*16
    const int b_kof = 8 * ((lane >> 3) & 1);            // + ks

    auto load_chunk = [&](int i, int buf) {
        const int seg = i / CH, kc = i % CH;
        const int aoff = segA[seg] + kc * KC;
        const int boff = segB[seg] + kc * KC;
        const uint32_t sa = smem_u + buf * BUFB;
        const uint32_t sb = sa + STAGEB;
#pragma unroll
        for (int j = 0; j < 4; ++j) {
            const int row = lrow0 + 32 * j;
            cpa16(sa + row * SROWB + lc16 * 16, Ab + (size_t)row * RS + aoff + lc16 * 8);
            cpa16(sb + row * SROWB + lc16 * 16, Bb + (size_t)row * RS + boff + lc16 * 8);
        }
        cp_commit();
    };

    load_chunk(0, 0);

    for (int i = 0; i < NCH; ++i) {
        if (i + 1 < NCH) { load_chunk(i + 1, (i + 1) & 1); cp_wait<1>(); }
        else             { cp_wait<0>(); }
        __syncthreads();

        const uint32_t sa = smem_u + (i & 1) * BUFB;
        const uint32_t sb = sa + STAGEB;
#pragma unroll
        for (int ks = 0; ks < KC; ks += 16) {
            uint32_t af[4][4];
#pragma unroll
            for (int mt = 0; mt < 4; ++mt)
                ldsm4(af[mt], sa + (a_row + mt * 16) * SROWB + (ks + a_kof) * 2);
            uint32_t bfr[2][4];
#pragma unroll
            for (int np = 0; np < 2; ++np)
                ldsm4(bfr[np], sb + (b_row + np * 16) * SROWB + (ks + b_kof) * 2);
#pragma unroll
            for (int mt = 0; mt < 4; ++mt)
#pragma unroll
                for (int nt = 0; nt < 4; ++nt)
                    mma_bf16(acc[mt][nt], af[mt],
                             bfr[nt >> 1][2 * (nt & 1)], bfr[nt >> 1][2 * (nt & 1) + 1]);
        }
        __syncthreads();
    }

    // ---- Epilogue: accum frags -> padded smem stage -> global ----
    float* st = reinterpret_cast<float*>(dynsmem);
    const int lr  = lane >> 2;
    const int lc2 = 2 * (lane & 3);
#pragma unroll
    for (int mt = 0; mt < 4; ++mt)
#pragma unroll
        for (int nt = 0; nt < 4; ++nt) {
            const int gr = warp_m * 64 + mt * 16 + lr;
            const int gc = warp_n * 32 + nt * 8 + lc2;
            st[gr * 129 + gc]           = acc[mt][nt][0];
            st[gr * 129 + gc + 1]       = acc[mt][nt][1];
            st[(gr + 8) * 129 + gc]     = acc[mt][nt][2];
            st[(gr + 8) * 129 + gc + 1] = acc[mt][nt][3];
        }
    __syncthreads();

    if (EPI == 0) {
        bf16* outp = reinterpret_cast<bf16*>(Out) + (size_t)b * oBatch;
        for (int idx = tid; idx < 128 * 64; idx += 256) {
            const int r  = idx >> 6;
            const int c2 = (idx & 63) * 2;
            float f0 = st[r * 129 + c2];
            float f1 = st[r * 129 + c2 + 1];
            if (BIAS == 1) { f0 += bias[n0 + c2]; f1 += bias[n0 + c2 + 1]; }
            if (BIAS == 2) { const float bb = bias[m0 + r]; f0 += bb; f1 += bb; }
            bf16 h0, l0, h1, l1;
            split2(f0, h0, l0); split2(f1, h1, l1);
            const size_t base = (size_t)(m0 + r) * outRowStride + n0;
            __nv_bfloat162 hv; hv.x = h0; hv.y = h1;
            __nv_bfloat162 lv; lv.x = l0; lv.y = l1;
            *reinterpret_cast<__nv_bfloat162*>(outp + base + c2) = hv;
            *reinterpret_cast<__nv_bfloat162*>(outp + base + loOff + c2) = lv;
        }
    } else if (EPI == 1) {
        const float SCALE = 0.05103103630798288f;  // 1/sqrt(384)
        float* outp = reinterpret_cast<float*>(Out) + (size_t)b * oBatch;
        for (int idx = tid; idx < 128 * 32; idx += 256) {
            const int r  = idx >> 5;
            const int c4 = (idx & 31) * 4;
            float4 v;
            v.x = st[r * 129 + c4]     * SCALE;
            v.y = st[r * 129 + c4 + 1] * SCALE;
            v.z = st[r * 129 + c4 + 2] * SCALE;
            v.w = st[r * 129 + c4 + 3] * SCALE;
            *reinterpret_cast<float4*>(&outp[(size_t)(m0 + r) * outRowStride + n0 + c4]) = v;
        }
    } else {
        // final: D[n][d] -> out[b][d][n] (+ bias by d = col)
        float* outp = reinterpret_cast<float*>(Out) + (size_t)b * oBatch;
        for (int idx = tid; idx < 128 * 128; idx += 256) {
            const int r = idx & 127;       // n within tile (coalesced in out)
            const int c = idx >> 7;        // d within tile
            float f = st[r * 129 + c];
            if (BIAS == 1) f += bias[n0 + c];
            outp[(size_t)(n0 + c) * outRowStride + m0 + r] = f;
        }
    }
}

// ---------------------------------------------------------------------------
// Softmax over m, writes split-bf16 P: [n][ hi(m) | lo(m) ]
// ---------------------------------------------------------------------------
__global__ void softmax_kernel()
{
    const size_t row = blockIdx.x;
    const float* p = g_Sc + row * NP;
    bf16* po = g_Ps + row * (size_t)(2 * NP);
    const int t = threadIdx.x;

    float4 a = *reinterpret_cast<const float4*>(&p[t * 4]);
    float4 c = *reinterpret_cast<const float4*>(&p[512 + t * 4]);
    float v[8] = {a.x, a.y, a.z, a.w, c.x, c.y, c.z, c.w};

    float m = v[0];
#pragma unroll
    for (int i = 1; i < 8; ++i) m = fmaxf(m, v[i]);
#pragma unroll
    for (int o = 16; o > 0; o >>= 1) m = fmaxf(m, __shfl_xor_sync(0xffffffffu, m, o));

    __shared__ float rmax[4];
    __shared__ float rsum[4];
    const int w = t >> 5, l = t & 31;
    if (l == 0) rmax[w] = m;
    __syncthreads();
    const float mr = fmaxf(fmaxf(rmax[0], rmax[1]), fmaxf(rmax[2], rmax[3]));

    float s = 0.f;
#pragma unroll
    for (int i = 0; i < 8; ++i) { v[i] = __expf(v[i] - mr); s += v[i]; }
#pragma unroll
    for (int o = 16; o > 0; o >>= 1) s += __shfl_xor_sync(0xffffffffu, s, o);
    if (l == 0) rsum[w] = s;
    __syncthreads();
    const float inv = 1.f / (rsum[0] + rsum[1] + rsum[2] + rsum[3]);

#pragma unroll
    for (int half = 0; half < 2; ++half) {
        const int col = half * 512 + t * 4;
#pragma unroll
        for (int k2 = 0; k2 < 2; ++k2) {
            float f0 = v[half * 4 + k2 * 2 + 0] * inv;
            float f1 = v[half * 4 + k2 * 2 + 1] * inv;
            bf16 h0, l0, h1, l1;
            split2(f0, h0, l0); split2(f1, h1, l1);
            __nv_bfloat162 hv; hv.x = h0; hv.y = h1;
            __nv_bfloat162 lv; lv.x = l0; lv.y = l1;
            *reinterpret_cast<__nv_bfloat162*>(po + col + k2 * 2) = hv;
            *reinterpret_cast<__nv_bfloat162*>(po + NP + col + k2 * 2) = lv;
        }
    }
}

// ---------------------------------------------------------------------------
// Launch
// ---------------------------------------------------------------------------
extern "C" void kernel_launch(void* const* d_in, const int* in_sizes, int n_in,
                              void* d_out, int out_size)
{
    const float* rgb = (const float*)d_in[0];
    const float* ms  = (const float*)d_in[1];
    const float* Wq  = (const float*)d_in[2];
    const float* bq  = (const float*)d_in[3];
    const float* Wk  = (const float*)d_in[4];
    const float* bk  = (const float*)d_in[5];
    const float* Wv  = (const float*)d_in[6];
    const float* bv  = (const float*)d_in[7];
    const float* Wf  = (const float*)d_in[8];
    const float* bf  = (const float*)d_in[9];
    float* out = (float*)d_out;

    void *p_rgbT, *p_msT, *p_Wqs, *p_Wks, *p_Wvs, *p_Wfs;
    void *p_qs, *p_ks, *p_vs, *p_Sc, *p_Ps, *p_os;
    cudaGetSymbolAddress(&p_rgbT, g_rgbT);
    cudaGetSymbolAddress(&p_msT,  g_msT);
    cudaGetSymbolAddress(&p_Wqs,  g_Wqs);
    cudaGetSymbolAddress(&p_Wks,  g_Wks);
    cudaGetSymbolAddress(&p_Wvs,  g_Wvs);
    cudaGetSymbolAddress(&p_Wfs,  g_Wfs);
    cudaGetSymbolAddress(&p_qs,   g_qs);
    cudaGetSymbolAddress(&p_ks,   g_ks);
    cudaGetSymbolAddress(&p_vs,   g_vs);
    cudaGetSymbolAddress(&p_Sc,   g_Sc);
    cudaGetSymbolAddress(&p_Ps,   g_Ps);
    cudaGetSymbolAddress(&p_os,   g_os);

    cudaFuncSetAttribute(mm_kernel<384, 0, 1>,  cudaFuncAttributeMaxDynamicSharedMemorySize, SMEMSZ);
    cudaFuncSetAttribute(mm_kernel<384, 0, 2>,  cudaFuncAttributeMaxDynamicSharedMemorySize, SMEMSZ);
    cudaFuncSetAttribute(mm_kernel<384, 1, 0>,  cudaFuncAttributeMaxDynamicSharedMemorySize, SMEMSZ);
    cudaFuncSetAttribute(mm_kernel<1024, 0, 0>, cudaFuncAttributeMaxDynamicSharedMemorySize, SMEMSZ);
    cudaFuncSetAttribute(mm_kernel<384, 2, 1>,  cudaFuncAttributeMaxDynamicSharedMemorySize, SMEMSZ);

    // pack (2 launches)                               launch idx 0, 1
    pack_x<<<dim3(32, 12, 2 * NB), dim3(32, 8)>>>(rgb, ms);
    pack_w4<<<dim3(576, 4), 256>>>(Wq, Wk, Wv, Wf);

    const size_t xB = (size_t)NP * (2 * CD);
    const size_t vB = (size_t)CD * (2 * NP);
    const size_t sB = (size_t)NP * NP;

    // q = rgb^T * Wq^T : D[n][d]                      launch idx 2
    mm_kernel<384, 0, 1><<<dim3(3, 8, NB), 256, SMEMSZ>>>(
        (bf16*)p_rgbT, (bf16*)p_Wqs, p_qs, bq, xB, 0, xB, 2 * CD, CD);
    // k = ms^T * Wk^T : D[m][d]                       launch idx 3
    mm_kernel<384, 0, 1><<<dim3(3, 8, NB), 256, SMEMSZ>>>(
        (bf16*)p_msT, (bf16*)p_Wks, p_ks, bk, xB, 0, xB, 2 * CD, CD);
    // v = Wv * ms : D[c][m]  (bias by row)            launch idx 4
    mm_kernel<384, 0, 2><<<dim3(8, 3, NB), 256, SMEMSZ>>>(
        (bf16*)p_Wvs, (bf16*)p_msT, p_vs, bv, 0, xB, vB, 2 * NP, NP);
    // scores: D[n][m] fp32 * 1/sqrt(C)                launch idx 5  <-- ncu -s 5
    mm_kernel<384, 1, 0><<<dim3(8, 8, NB), 256, SMEMSZ>>>(
        (bf16*)p_qs, (bf16*)p_ks, p_Sc, nullptr, xB, xB, sB, NP, 0);
    // softmax + split-pack P                          launch idx 6
    softmax_kernel<<<NB * NP, 128>>>();
    // O^T[n][c] = P * v^T                             launch idx 7
    mm_kernel<1024, 0, 0><<<dim3(3, 8, NB), 256, SMEMSZ>>>(
        (bf16*)p_Ps, (bf16*)p_vs, p_os, nullptr, (size_t)NP * (2 * NP), vB, xB, 2 * CD, CD);
    // final: D[n][d] -> out[b][d][n] (+bias by d)     launch idx 8
    mm_kernel<384, 2, 1><<<dim3(3, 8, NB), 256, SMEMSZ>>>(
        (bf16*)p_os, (bf16*)p_Wfs, out, bf, xB, 0, (size_t)CD * NP, NP, 0);
}

// round 7
// speedup vs baseline: 2.6524x; 1.0375x over previous
#include <cuda_runtime.h>
#include <cuda_bf16.h>
#include <math.h>
#include <stdint.h>

using bf16 = __nv_bfloat16;

constexpr int NB = 32;
constexpr int CD = 384;    // channels
constexpr int NP = 1024;   // pixels

// ---------------------------------------------------------------------------
// Device scratch (allocation-free). Split layout: [row][ hi(0..K-1) | lo(K..2K-1) ]
// ---------------------------------------------------------------------------
__device__ __align__(128) bf16  g_rgbT[(size_t)NB * NP * (2 * CD)];   // [b][n][c']
__device__ __align__(128) bf16  g_msT [(size_t)NB * NP * (2 * CD)];   // [b][n][c']
__device__ __align__(128) bf16  g_Wqs[CD * (2 * CD)];
__device__ __align__(128) bf16  g_Wks[CD * (2 * CD)];
__device__ __align__(128) bf16  g_Wvs[CD * (2 * CD)];
__device__ __align__(128) bf16  g_Wfs[CD * (2 * CD)];
__device__ __align__(128) bf16  g_qs[(size_t)NB * NP * (2 * CD)];     // [b][n][d']
__device__ __align__(128) bf16  g_ks[(size_t)NB * NP * (2 * CD)];     // [b][m][d']
__device__ __align__(128) bf16  g_vs[(size_t)NB * CD * (2 * NP)];     // [b][c][m']
__device__ __align__(128) float g_Sc[(size_t)NB * NP * NP];           // scores fp32
__device__ __align__(128) bf16  g_Ps[(size_t)NB * NP * (2 * NP)];     // softmax split
__device__ __align__(128) bf16  g_os[(size_t)NB * NP * (2 * CD)];     // [b][n][c']

// ---------------------------------------------------------------------------
// Base-target PTX helpers (sm_80-class: cp.async / ldmatrix / mma.sync)
// ---------------------------------------------------------------------------
__device__ __forceinline__ uint32_t su32(const void* p) {
    uint32_t a;
    asm("{ .reg .u64 t; cvta.to.shared.u64 t, %1; cvt.u32.u64 %0, t; }" : "=r"(a) : "l"(p));
    return a;
}
__device__ __forceinline__ void cpa16(uint32_t s, const void* g) {
    asm volatile("cp.async.cg.shared.global [%0], [%1], 16;" :: "r"(s), "l"(g));
}
__device__ __forceinline__ void cp_commit() {
    asm volatile("cp.async.commit_group;" ::: "memory");
}
template <int N>
__device__ __forceinline__ void cp_wait() {
    asm volatile("cp.async.wait_group %0;" :: "n"(N) : "memory");
}
__device__ __forceinline__ void ldsm4(uint32_t* r, uint32_t addr) {
    asm volatile("ldmatrix.sync.aligned.m8n8.x4.shared.b16 {%0,%1,%2,%3}, [%4];"
                 : "=r"(r[0]), "=r"(r[1]), "=r"(r[2]), "=r"(r[3]) : "r"(addr));
}
__device__ __forceinline__ void mma_bf16(float* d, const uint32_t* a, uint32_t b0, uint32_t b1) {
    asm volatile(
        "mma.sync.aligned.m16n8k16.row.col.f32.bf16.bf16.f32 "
        "{%0,%1,%2,%3}, {%4,%5,%6,%7}, {%8,%9}, {%0,%1,%2,%3};"
        : "+f"(d[0]), "+f"(d[1]), "+f"(d[2]), "+f"(d[3])
        : "r"(a[0]), "r"(a[1]), "r"(a[2]), "r"(a[3]), "r"(b0), "r"(b1));
}

__device__ __forceinline__ void split2(float f, bf16& h, bf16& l) {
    h = __float2bfloat16(f);
    l = __float2bfloat16(f - __bfloat162float(h));
}

// ---------------------------------------------------------------------------
// Pack kernels
// ---------------------------------------------------------------------------
__global__ void pack_x(const float* __restrict__ Xr, const float* __restrict__ Xm) {
    __shared__ float t[32][33];
    int z = blockIdx.z;
    const float* X = (z < NB) ? Xr : Xm;
    bf16* out = (z < NB) ? g_rgbT : g_msT;
    int b = (z < NB) ? z : z - NB;
    int n0 = blockIdx.x * 32, c0 = blockIdx.y * 32;
    int tx = threadIdx.x, ty = threadIdx.y;   // (32, 8)
    const float* Xb = X + (size_t)b * CD * NP;
    bf16* Ob = out + (size_t)b * NP * (2 * CD);
#pragma unroll
    for (int i = 0; i < 4; ++i)
        t[ty + 8 * i][tx] = Xb[(size_t)(c0 + ty + 8 * i) * NP + n0 + tx];
    __syncthreads();
#pragma unroll
    for (int i = 0; i < 4; ++i) {
        int n = n0 + ty + 8 * i;
        float f = t[tx][ty + 8 * i];
        bf16 h, l; split2(f, h, l);
        Ob[(size_t)n * (2 * CD) + c0 + tx] = h;
        Ob[(size_t)n * (2 * CD) + CD + c0 + tx] = l;
    }
}

__global__ void pack_w4(const float* __restrict__ W0, const float* __restrict__ W1,
                        const float* __restrict__ W2, const float* __restrict__ W3) {
    int idx = blockIdx.x * 256 + threadIdx.x;   // 384*384 = 576*256
    int which = blockIdx.y;
    const float* W = (which == 0) ? W0 : (which == 1) ? W1 : (which == 2) ? W2 : W3;
    bf16* out = (which == 0) ? g_Wqs : (which == 1) ? g_Wks : (which == 2) ? g_Wvs : g_Wfs;
    int r = idx / CD, c = idx % CD;
    float f = W[idx];
    bf16 h, l; split2(f, h, l);
    out[(size_t)r * (2 * CD) + c] = h;
    out[(size_t)r * (2 * CD) + CD + c] = l;
}

// ---------------------------------------------------------------------------
// Shared GEMM mainloop: 3-stage cp.async ring, 1 barrier/chunk, split-bf16 3-pass.
// ---------------------------------------------------------------------------
constexpr int KC     = 64;                 // K elems per chunk
constexpr int SROWB  = 144;                // 64 bf16 = 128B + 16B pad (conflict-free ldsm)
constexpr int STAGEB = 128 * SROWB;        // 18432 per operand
constexpr int BUFB   = 2 * STAGEB;         // A+B per stage: 36864
constexpr int NSTAGE = 3;
constexpr int SMEMSZ = NSTAGE * BUFB;      // 110592 (>= epilogue 128*129*4=66048)

template <int K>
__device__ __forceinline__ void gemm_main(const bf16* __restrict__ Ab,
                                          const bf16* __restrict__ Bb,
                                          char* dynsmem, float (&acc)[4][4][4])
{
    constexpr int CH  = K / KC;
    constexpr int NCH = 3 * CH;
    constexpr int RS  = 2 * K;

    const int tid  = threadIdx.x;
    const int wid  = tid >> 5;
    const int lane = tid & 31;
    const int warp_m = wid & 1;
    const int warp_n = wid >> 1;

    const uint32_t smem_u = su32(dynsmem);

    const int segA[3] = { 0, 0, K };
    const int segB[3] = { 0, K, 0 };

    const int lrow0 = tid >> 3;
    const int lc16  = tid & 7;

    const int a_row = warp_m * 64 + (lane & 15);
    const int a_kof = 8 * (lane >> 4);
    const int b_row = warp_n * 32 + (lane & 7) + 8 * (lane >> 4);
    const int b_kof = 8 * ((lane >> 3) & 1);

    auto load_chunk = [&](int i) {
        const int seg = i / CH, kc = i % CH;
        const int aoff = segA[seg] + kc * KC;
        const int boff = segB[seg] + kc * KC;
        const uint32_t sa = smem_u + (i % NSTAGE) * BUFB;
        const uint32_t sb = sa + STAGEB;
#pragma unroll
        for (int j = 0; j < 4; ++j) {
            const int row = lrow0 + 32 * j;
            cpa16(sa + row * SROWB + lc16 * 16, Ab + (size_t)row * RS + aoff + lc16 * 8);
            cpa16(sb + row * SROWB + lc16 * 16, Bb + (size_t)row * RS + boff + lc16 * 8);
        }
        cp_commit();
    };

    load_chunk(0);
    load_chunk(1);

    for (int i = 0; i < NCH; ++i) {
        if (i + 1 < NCH) cp_wait<1>();
        else             cp_wait<0>();
        __syncthreads();
        if (i + 2 < NCH) load_chunk(i + 2);

        const uint32_t sa = smem_u + (i % NSTAGE) * BUFB;
        const uint32_t sb = sa + STAGEB;
#pragma unroll
        for (int ks = 0; ks < KC; ks += 16) {
            uint32_t af[4][4];
#pragma unroll
            for (int mt = 0; mt < 4; ++mt)
                ldsm4(af[mt], sa + (a_row + mt * 16) * SROWB + (ks + a_kof) * 2);
            uint32_t bfr[2][4];
#pragma unroll
            for (int np = 0; np < 2; ++np)
                ldsm4(bfr[np], sb + (b_row + np * 16) * SROWB + (ks + b_kof) * 2);
#pragma unroll
            for (int mt = 0; mt < 4; ++mt)
#pragma unroll
                for (int nt = 0; nt < 4; ++nt)
                    mma_bf16(acc[mt][nt], af[mt],
                             bfr[nt >> 1][2 * (nt & 1)], bfr[nt >> 1][2 * (nt & 1) + 1]);
        }
    }
    __syncthreads();   // last compute done in all warps before smem reuse
}

// stage accumulators into padded fp32 smem
__device__ __forceinline__ void stage_acc(float* st, float (&acc)[4][4][4]) {
    const int tid  = threadIdx.x;
    const int wid  = tid >> 5;
    const int lane = tid & 31;
    const int warp_m = wid & 1;
    const int warp_n = wid >> 1;
    const int lr  = lane >> 2;
    const int lc2 = 2 * (lane & 3);
#pragma unroll
    for (int mt = 0; mt < 4; ++mt)
#pragma unroll
        for (int nt = 0; nt < 4; ++nt) {
            const int gr = warp_m * 64 + mt * 16 + lr;
            const int gc = warp_n * 32 + nt * 8 + lc2;
            st[gr * 129 + gc]           = acc[mt][nt][0];
            st[gr * 129 + gc + 1]       = acc[mt][nt][1];
            st[(gr + 8) * 129 + gc]     = acc[mt][nt][2];
            st[(gr + 8) * 129 + gc + 1] = acc[mt][nt][3];
        }
    __syncthreads();
}

// ---------------------------------------------------------------------------
// Merged Q/K/V projection kernel. grid (3, 8, 3*NB).
// which = z/NB: 0 q (rgb*Wq -> [n][d]), 1 k (ms*Wk -> [m][d]), 2 v (Wv*ms -> [c][m])
// ---------------------------------------------------------------------------
__global__ __launch_bounds__(256, 2)
void qkv_kernel(const float* __restrict__ bq, const float* __restrict__ bk,
                const float* __restrict__ bv)
{
    extern __shared__ __align__(16) char dynsmem[];
    constexpr int RS = 2 * CD;
    const size_t xB = (size_t)NP * (2 * CD);
    const size_t vB = (size_t)CD * (2 * NP);

    const int zb = blockIdx.z;
    const int which = zb >> 5;          // /NB
    const int b = zb & 31;

    int m0, n0;
    const bf16 *Ab, *Bb;
    bf16* outp;
    const float* bias;
    int outRowStride, loOff;
    bool rowBias;

    if (which == 0) {
        m0 = blockIdx.y * 128; n0 = blockIdx.x * 128;
        Ab = g_rgbT + b * xB + (size_t)m0 * RS;
        Bb = g_Wqs + (size_t)n0 * RS;
        outp = g_qs + b * xB; bias = bq;
        outRowStride = 2 * CD; loOff = CD; rowBias = false;
    } else if (which == 1) {
        m0 = blockIdx.y * 128; n0 = blockIdx.x * 128;
        Ab = g_msT + b * xB + (size_t)m0 * RS;
        Bb = g_Wks + (size_t)n0 * RS;
        outp = g_ks + b * xB; bias = bk;
        outRowStride = 2 * CD; loOff = CD; rowBias = false;
    } else {
        m0 = blockIdx.x * 128; n0 = blockIdx.y * 128;   // A = weights (3 c-tiles), B = ms (8 m-tiles)
        Ab = g_Wvs + (size_t)m0 * RS;
        Bb = g_msT + b * xB + (size_t)n0 * RS;
        outp = g_vs + b * vB; bias = bv;
        outRowStride = 2 * NP; loOff = NP; rowBias = true;
    }

    float acc[4][4][4] = {};
    gemm_main<CD>(Ab, Bb, dynsmem, acc);

    float* st = reinterpret_cast<float*>(dynsmem);
    stage_acc(st, acc);

    const int tid = threadIdx.x;
    for (int idx = tid; idx < 128 * 64; idx += 256) {
        const int r  = idx >> 6;
        const int c2 = (idx & 63) * 2;
        float f0 = st[r * 129 + c2];
        float f1 = st[r * 129 + c2 + 1];
        if (rowBias) { const float bb = bias[m0 + r]; f0 += bb; f1 += bb; }
        else         { f0 += bias[n0 + c2]; f1 += bias[n0 + c2 + 1]; }
        bf16 h0, l0, h1, l1;
        split2(f0, h0, l0); split2(f1, h1, l1);
        const size_t base = (size_t)(m0 + r) * outRowStride + n0;
        __nv_bfloat162 hv; hv.x = h0; hv.y = h1;
        __nv_bfloat162 lv; lv.x = l0; lv.y = l1;
        *reinterpret_cast<__nv_bfloat162*>(outp + base + c2) = hv;
        *reinterpret_cast<__nv_bfloat162*>(outp + base + loOff + c2) = lv;
    }
}

// ---------------------------------------------------------------------------
// Generic GEMM kernel for scores / AV / final.
// EPI: 0 split-bf16 (no bias), 1 fp32*scale, 2 fp32 transposed + col bias.
// ---------------------------------------------------------------------------
template <int K, int EPI>
__global__ __launch_bounds__(256, 2)
void mm_kernel(const bf16* __restrict__ A, const bf16* __restrict__ B,
               void* __restrict__ Out, const float* __restrict__ bias,
               size_t aBatch, size_t bBatch, size_t oBatch,
               int outRowStride, int loOff)
{
    extern __shared__ __align__(16) char dynsmem[];
    constexpr int RS = 2 * K;

    const int tid = threadIdx.x;
    const int m0 = blockIdx.y * 128;
    const int n0 = blockIdx.x * 128;
    const int b  = blockIdx.z;

    const bf16* Ab = A + (size_t)b * aBatch + (size_t)m0 * RS;
    const bf16* Bb = B + (size_t)b * bBatch + (size_t)n0 * RS;

    float acc[4][4][4] = {};
    gemm_main<K>(Ab, Bb, dynsmem, acc);

    float* st = reinterpret_cast<float*>(dynsmem);
    stage_acc(st, acc);

    if (EPI == 0) {
        bf16* outp = reinterpret_cast<bf16*>(Out) + (size_t)b * oBatch;
        for (int idx = tid; idx < 128 * 64; idx += 256) {
            const int r  = idx >> 6;
            const int c2 = (idx & 63) * 2;
            float f0 = st[r * 129 + c2];
            float f1 = st[r * 129 + c2 + 1];
            bf16 h0, l0, h1, l1;
            split2(f0, h0, l0); split2(f1, h1, l1);
            const size_t base = (size_t)(m0 + r) * outRowStride + n0;
            __nv_bfloat162 hv; hv.x = h0; hv.y = h1;
            __nv_bfloat162 lv; lv.x = l0; lv.y = l1;
            *reinterpret_cast<__nv_bfloat162*>(outp + base + c2) = hv;
            *reinterpret_cast<__nv_bfloat162*>(outp + base + loOff + c2) = lv;
        }
    } else if (EPI == 1) {
        const float SCALE = 0.05103103630798288f;  // 1/sqrt(384)
        float* outp = reinterpret_cast<float*>(Out) + (size_t)b * oBatch;
        for (int idx = tid; idx < 128 * 32; idx += 256) {
            const int r  = idx >> 5;
            const int c4 = (idx & 31) * 4;
            float4 v;
            v.x = st[r * 129 + c4]     * SCALE;
            v.y = st[r * 129 + c4 + 1] * SCALE;
            v.z = st[r * 129 + c4 + 2] * SCALE;
            v.w = st[r * 129 + c4 + 3] * SCALE;
            *reinterpret_cast<float4*>(&outp[(size_t)(m0 + r) * outRowStride + n0 + c4]) = v;
        }
    } else {
        float* outp = reinterpret_cast<float*>(Out) + (size_t)b * oBatch;
        for (int idx = tid; idx < 128 * 128; idx += 256) {
            const int r = idx & 127;
            const int c = idx >> 7;
            float f = st[r * 129 + c] + bias[n0 + c];
            outp[(size_t)(n0 + c) * outRowStride + m0 + r] = f;
        }
    }
}

// ---------------------------------------------------------------------------
// Softmax over m, writes split-bf16 P: [n][ hi(m) | lo(m) ]
// ---------------------------------------------------------------------------
__global__ void softmax_kernel()
{
    const size_t row = blockIdx.x;
    const float* p = g_Sc + row * NP;
    bf16* po = g_Ps + row * (size_t)(2 * NP);
    const int t = threadIdx.x;

    float4 a = *reinterpret_cast<const float4*>(&p[t * 4]);
    float4 c = *reinterpret_cast<const float4*>(&p[512 + t * 4]);
    float v[8] = {a.x, a.y, a.z, a.w, c.x, c.y, c.z, c.w};

    float m = v[0];
#pragma unroll
    for (int i = 1; i < 8; ++i) m = fmaxf(m, v[i]);
#pragma unroll
    for (int o = 16; o > 0; o >>= 1) m = fmaxf(m, __shfl_xor_sync(0xffffffffu, m, o));

    __shared__ float rmax[4];
    __shared__ float rsum[4];
    const int w = t >> 5, l = t & 31;
    if (l == 0) rmax[w] = m;
    __syncthreads();
    const float mr = fmaxf(fmaxf(rmax[0], rmax[1]), fmaxf(rmax[2], rmax[3]));

    float s = 0.f;
#pragma unroll
    for (int i = 0; i < 8; ++i) { v[i] = __expf(v[i] - mr); s += v[i]; }
#pragma unroll
    for (int o = 16; o > 0; o >>= 1) s += __shfl_xor_sync(0xffffffffu, s, o);
    if (l == 0) rsum[w] = s;
    __syncthreads();
    const float inv = 1.f / (rsum[0] + rsum[1] + rsum[2] + rsum[3]);

#pragma unroll
    for (int half = 0; half < 2; ++half) {
        const int col = half * 512 + t * 4;
#pragma unroll
        for (int k2 = 0; k2 < 2; ++k2) {
            float f0 = v[half * 4 + k2 * 2 + 0] * inv;
            float f1 = v[half * 4 + k2 * 2 + 1] * inv;
            bf16 h0, l0, h1, l1;
            split2(f0, h0, l0); split2(f1, h1, l1);
            __nv_bfloat162 hv; hv.x = h0; hv.y = h1;
            __nv_bfloat162 lv; lv.x = l0; lv.y = l1;
            *reinterpret_cast<__nv_bfloat162*>(po + col + k2 * 2) = hv;
            *reinterpret_cast<__nv_bfloat162*>(po + NP + col + k2 * 2) = lv;
        }
    }
}

// ---------------------------------------------------------------------------
// Launch
// ---------------------------------------------------------------------------
extern "C" void kernel_launch(void* const* d_in, const int* in_sizes, int n_in,
                              void* d_out, int out_size)
{
    const float* rgb = (const float*)d_in[0];
    const float* ms  = (const float*)d_in[1];
    const float* Wq  = (const float*)d_in[2];
    const float* bq  = (const float*)d_in[3];
    const float* Wk  = (const float*)d_in[4];
    const float* bk  = (const float*)d_in[5];
    const float* Wv  = (const float*)d_in[6];
    const float* bv  = (const float*)d_in[7];
    const float* Wf  = (const float*)d_in[8];
    const float* bf  = (const float*)d_in[9];
    float* out = (float*)d_out;

    void *p_qs, *p_ks, *p_vs, *p_Sc, *p_Ps, *p_os, *p_Wfs;
    cudaGetSymbolAddress(&p_qs,  g_qs);
    cudaGetSymbolAddress(&p_ks,  g_ks);
    cudaGetSymbolAddress(&p_vs,  g_vs);
    cudaGetSymbolAddress(&p_Sc,  g_Sc);
    cudaGetSymbolAddress(&p_Ps,  g_Ps);
    cudaGetSymbolAddress(&p_os,  g_os);
    cudaGetSymbolAddress(&p_Wfs, g_Wfs);

    cudaFuncSetAttribute(qkv_kernel,         cudaFuncAttributeMaxDynamicSharedMemorySize, SMEMSZ);
    cudaFuncSetAttribute(mm_kernel<384, 1>,  cudaFuncAttributeMaxDynamicSharedMemorySize, SMEMSZ);
    cudaFuncSetAttribute(mm_kernel<1024, 0>, cudaFuncAttributeMaxDynamicSharedMemorySize, SMEMSZ);
    cudaFuncSetAttribute(mm_kernel<384, 2>,  cudaFuncAttributeMaxDynamicSharedMemorySize, SMEMSZ);

    const size_t xB = (size_t)NP * (2 * CD);
    const size_t vB = (size_t)CD * (2 * NP);
    const size_t sB = (size_t)NP * NP;

    // launch idx 0, 1: pack
    pack_x<<<dim3(32, 12, 2 * NB), dim3(32, 8)>>>(rgb, ms);
    pack_w4<<<dim3(576, 4), 256>>>(Wq, Wk, Wv, Wf);
    // launch idx 2: fused q/k/v projections
    qkv_kernel<<<dim3(3, 8, 3 * NB), 256, SMEMSZ>>>(bq, bk, bv);
    // launch idx 3: scores D[n][m] = q.k / sqrt(C)
    mm_kernel<384, 1><<<dim3(8, 8, NB), 256, SMEMSZ>>>(
        (bf16*)p_qs, (bf16*)p_ks, p_Sc, nullptr, xB, xB, sB, NP, 0);
    // launch idx 4: softmax + split-pack P
    softmax_kernel<<<NB * NP, 128>>>();
    // launch idx 5: O^T[n][c] = P * v^T   <-- ncu -s 5 profiles this
    mm_kernel<1024, 0><<<dim3(3, 8, NB), 256, SMEMSZ>>>(
        (bf16*)p_Ps, (bf16*)p_vs, p_os, nullptr, (size_t)NP * (2 * NP), vB, xB, 2 * CD, CD);
    // launch idx 6: final D[n][d] -> out[b][d][n] (+bias by d)
    mm_kernel<384, 2><<<dim3(3, 8, NB), 256, SMEMSZ>>>(
        (bf16*)p_os, (bf16*)p_Wfs, out, bf, xB, 0, (size_t)CD * NP, NP, 0);
}